// round 2
// baseline (speedup 1.0000x reference)
#include <cuda_runtime.h>
#include <cstdint>

// Problem constants
#define BB     8
#define RR     2048
#define CC     4096
#define NROWS  (BB * RR)            // 16384 score rows
#define WORDS  (CC / 32)            // 128 mask words per row
#define K_FRONT 1228                // int(4096*0.30)
#define K_RAND  409                 // int(4096*0.10)

// ---- scratch (device globals; no allocation allowed) ----
__device__ uint32_t g_smask[NROWS * WORDS];   // student keep-bits, 8 MB
__device__ uint32_t g_front0[BB * WORDS];     // front-sel bits for row 0 of each batch

// ---- threefry2x32, key = (0, 42) baked in ----
// ks = [0, 42, 0x1BD11BDA ^ 0 ^ 42 = 0x1BD11BF0]
__device__ __forceinline__ void threefry_0_42(uint32_t c0, uint32_t c1,
                                              uint32_t& o0, uint32_t& o1) {
    uint32_t x0 = c0 + 0u;
    uint32_t x1 = c1 + 42u;
#define TF_RND(r) { x0 += x1; x1 = __funnelshift_l(x1, x1, (r)); x1 ^= x0; }
    TF_RND(13) TF_RND(15) TF_RND(26) TF_RND(6)
    x0 += 42u;          x1 += 0x1BD11BF1u;   // ks1, ks2+1
    TF_RND(17) TF_RND(29) TF_RND(16) TF_RND(24)
    x0 += 0x1BD11BF0u;  x1 += 2u;            // ks2, ks0+2
    TF_RND(13) TF_RND(15) TF_RND(26) TF_RND(6)
    x0 += 0u;           x1 += 45u;           // ks0, ks1+3
    TF_RND(17) TF_RND(29) TF_RND(16) TF_RND(24)
    x0 += 42u;          x1 += 0x1BD11BF4u;   // ks1, ks2+4
    TF_RND(13) TF_RND(15) TF_RND(26) TF_RND(6)
    x0 += 0x1BD11BF0u;  x1 += 5u;            // ks2, ks0+5
#undef TF_RND
    o0 = x0; o1 = x1;
}

// Ordering key of jax.random.uniform at flat index g:
// uniform ordering == ordering of bits>>9 == ordering of (bits & ~0x1FF).
// Keep it left-aligned (low 9 bits zero) so 8-bit top-down radix works on it.
__device__ __forceinline__ uint32_t rand_key(uint32_t g) {
    uint32_t o0, o1;
    threefry_0_42(0u, g, o0, o1);
    return (o0 ^ o1) & 0xFFFFFE00u;
}

__device__ __forceinline__ uint32_t warp_exscan(uint32_t v, int lane) {
    uint32_t x = v;
#pragma unroll
    for (int d = 1; d < 32; d <<= 1) {
        uint32_t y = __shfl_up_sync(0xFFFFFFFFu, x, d);
        if (lane >= d) x += y;
    }
    return x - v;
}

#define T1  512
#define EPT 8   // 512*8 = 4096 elems

// Top-down 8-bit radix select of rank K-1 over per-thread key array.
// rmax != 0 restricts participation to keys < rmax (a value cut, so ranks are
// preserved). Pass-0 uses warp-aggregated atomics (match_any) to kill
// contention. Returns T (threshold value, low bits of unresolved positions
// are zero for our key types) and need (# of ==T elements taken, lowest idx first).
__device__ __forceinline__ void radix_sel(const uint32_t (&key)[EPT], uint32_t rmax,
                                          uint32_t K, int npass, int t, int lane,
                                          uint32_t* hist, uint32_t* s_ctl,
                                          uint32_t& T, uint32_t& need) {
    uint32_t prefix = 0, kk = K - 1;
    for (int pass = 0; pass < npass; pass++) {
        const int shift = 32 - 8 * (pass + 1);
        if (t < 256) hist[t] = 0;
        __syncthreads();
#pragma unroll
        for (int j = 0; j < EPT; j++) {
            uint32_t k = key[j];
            bool part = (rmax == 0u || k < rmax) &&
                        (pass == 0 || (k >> (shift + 8)) == prefix);
            uint32_t bucket = part ? ((k >> shift) & 255u) : 0xFFFFFFFFu;
            uint32_t mm = __match_any_sync(0xFFFFFFFFu, bucket);
            if (part && lane == (__ffs(mm) - 1))
                atomicAdd(&hist[bucket], (uint32_t)__popc(mm));
        }
        __syncthreads();
        if (t < 32) {
            uint32_t h[8]; uint32_t sum = 0;
#pragma unroll
            for (int b2 = 0; b2 < 8; b2++) { h[b2] = hist[8 * t + b2]; sum += h[b2]; }
            uint32_t run = warp_exscan(sum, t);
#pragma unroll
            for (int b2 = 0; b2 < 8; b2++) {
                if (kk >= run && kk < run + h[b2]) {
                    s_ctl[0] = (prefix << 8) | (uint32_t)(8 * t + b2);
                    s_ctl[1] = kk - run;
                }
                run += h[b2];
            }
        }
        __syncthreads();
        prefix = s_ctl[0];
        kk = s_ctl[1];
        __syncthreads();
    }
    T = prefix << (32 - 8 * npass);
    need = kk + 1;
}

// ============================================================================
// Kernel 1: one block per score row. Computes front & rand thresholds and
// writes packed keep-masks.
// ============================================================================
__global__ __launch_bounds__(T1) void k1_select(const float* __restrict__ score) {
    const int q = blockIdx.x;              // row id in [0, 16384)
    const int t = threadIdx.x;
    const int wi = t >> 5, lane = t & 31;
    const uint32_t lmask_lt = (1u << lane) - 1u;

    const float* row = score + (size_t)q * CC;

    __shared__ uint32_t hist[256];
    __shared__ uint32_t s_ctl[2];
    __shared__ uint32_t s_warp[16];
    __shared__ uint32_t s_c0;
    __shared__ uint32_t s_pre[WORDS];
    __shared__ uint32_t s_pref_f[WORDS];

    // ---- load, key-ify, and ballot-count rand keys below the static pivot ----
    const uint32_t PIV = 1u << 29;   // top 3 key bits zero; E[count] = 512 >= 409
    uint32_t skey[EPT], rkey[EPT];
    uint32_t cnt = 0;
#pragma unroll
    for (int j = 0; j < EPT; j++) {
        int c = j * T1 + t;
        uint32_t u = __float_as_uint(row[c]);
        skey[j] = u ^ ((u & 0x80000000u) ? 0xFFFFFFFFu : 0x80000000u);
        rkey[j] = rand_key((uint32_t)(q * CC + c));
        cnt += __popc(__ballot_sync(0xFFFFFFFFu, rkey[j] < PIV));
    }
    if (lane == 0) s_warp[wi] = cnt;
    __syncthreads();
    if (t == 0) {
        uint32_t s = 0;
#pragma unroll
        for (int i = 0; i < 16; i++) s += s_warp[i];
        s_c0 = s;
    }
    __syncthreads();
    const uint32_t c0 = s_c0;

    // ---- selects ----
    uint32_t Tf, need_f, Tr, need_r;
    radix_sel(skey, 0u, (uint32_t)K_FRONT, 4, t, lane, hist, s_ctl, Tf, need_f);
    const uint32_t rmax = (c0 >= (uint32_t)K_RAND) ? PIV : 0u;  // exact fallback
    radix_sel(rkey, rmax, (uint32_t)K_RAND, 3, t, lane, hist, s_ctl, Tr, need_r);

    // ---- exact tie-break: per-word counts of ==T, then exclusive prefix ----
#pragma unroll
    for (int j = 0; j < EPT; j++) {
        uint32_t bf = __ballot_sync(0xFFFFFFFFu, skey[j] == Tf);
        uint32_t br = __ballot_sync(0xFFFFFFFFu, rkey[j] == Tr);
        if (lane == 0) {
            s_pref_f[j * 16 + wi] = __popc(bf);
            s_pre[j * 16 + wi]    = __popc(br);
        }
    }
    __syncthreads();
    if (t < 32) {  // exclusive prefix over 128 words, both arrays (4 words/lane)
        uint32_t a[4], b[4], sa = 0, sb = 0;
#pragma unroll
        for (int i = 0; i < 4; i++) { a[i] = s_pref_f[4 * t + i]; sa += a[i];
                                      b[i] = s_pre[4 * t + i];    sb += b[i]; }
        uint32_t ea = warp_exscan(sa, t), eb = warp_exscan(sb, t);
#pragma unroll
        for (int i = 0; i < 4; i++) {
            s_pref_f[4 * t + i] = ea; ea += a[i];
            s_pre[4 * t + i]    = eb; eb += b[i];
        }
    }
    __syncthreads();

    // ---- final mask computation + packed writes ----
    const bool is_row0 = ((q & (RR - 1)) == 0);
#pragma unroll
    for (int j = 0; j < EPT; j++) {
        const int w = j * 16 + wi;
        uint32_t bf = __ballot_sync(0xFFFFFFFFu, skey[j] == Tf);
        uint32_t br = __ballot_sync(0xFFFFFFFFu, rkey[j] == Tr);
        bool fsel = (skey[j] < Tf) ||
                    ((skey[j] == Tf) && (s_pref_f[w] + __popc(bf & lmask_lt) < need_f));
        bool rsel = (rkey[j] < Tr) ||
                    ((rkey[j] == Tr) && (s_pre[w] + __popc(br & lmask_lt) < need_r));
        uint32_t keep_w  = __ballot_sync(0xFFFFFFFFu, !(fsel || rsel));
        uint32_t front_w = __ballot_sync(0xFFFFFFFFu, fsel);
        if (lane == 0) {
            g_smask[q * WORDS + w] = keep_w;
            if (is_row0) g_front0[(q >> 11) * WORDS + w] = front_w;
        }
    }
}

// ============================================================================
// Kernel 2: per-batch [4096 x 2048] transpose with mask application.
// ============================================================================
__global__ __launch_bounds__(256) void k2_transpose(const float* __restrict__ score,
                                                    float* __restrict__ out_s,
                                                    float* __restrict__ out_t) {
    __shared__ float ss[32][33];
    __shared__ float st[32][33];
    const int b  = blockIdx.z;
    const int m0 = blockIdx.y * 32;
    const int j0 = blockIdx.x * 32;
    const int tx = threadIdx.x, ty = threadIdx.y;   // (32, 8)

    const float* base = score + (size_t)b * (RR * CC);
#pragma unroll
    for (int k = 0; k < 4; k++) {
        int m = m0 + ty + 8 * k;
        int j = j0 + tx;
        float v = base[(size_t)m * 2048 + j];
        int r = m >> 1;
        int c = ((m & 1) << 11) + j;
        int q = b * RR + r;
        uint32_t mw = g_smask[q * WORDS + (c >> 5)];
        float vs = ((mw >> (c & 31)) & 1u) ? v : 0.0f;
        float vt;
        if (r == 0) {
            uint32_t fw = g_front0[b * WORDS + (c >> 5)];
            vt = ((fw >> (c & 31)) & 1u) ? v : 0.0f;
        } else {
            vt = v;     // reference teacher-mask bug: rows 1.. stay all-ones
        }
        ss[ty + 8 * k][tx] = vs;
        st[ty + 8 * k][tx] = vt;
    }
    __syncthreads();

    float* os = out_s + (size_t)b * (RR * CC);
    float* ot = out_t + (size_t)b * (RR * CC);
#pragma unroll
    for (int k = 0; k < 4; k++) {
        int j = j0 + ty + 8 * k;
        int m = m0 + tx;
        os[(size_t)j * CC + m] = ss[tx][ty + 8 * k];
        ot[(size_t)j * CC + m] = st[tx][ty + 8 * k];
    }
}

// ============================================================================
extern "C" void kernel_launch(void* const* d_in, const int* in_sizes, int n_in,
                              void* d_out, int out_size) {
    const float* score = (const float*)d_in[0];
    float* out = (float*)d_out;
    float* out_teacher = out + (size_t)BB * RR * CC;

    k1_select<<<NROWS, T1>>>(score);

    dim3 grid(CC / 2 / 32, CC / 32, BB);
    dim3 blk(32, 8);
    k2_transpose<<<grid, blk>>>(score, out, out_teacher);
}

// round 3
// speedup vs baseline: 1.7186x; 1.7186x over previous
#include <cuda_runtime.h>
#include <cstdint>

// Problem constants
#define BB     8
#define RR     2048
#define CC     4096
#define NROWS  (BB * RR)            // 16384 score rows
#define WORDS  (CC / 32)            // 128 mask words per row
#define K_FRONT 1228                // int(4096*0.30)
#define K_RAND  409                 // int(4096*0.10)

// ---- scratch (device globals; no allocation allowed) ----
__device__ uint32_t g_smask[NROWS * WORDS];   // student keep-bits, 8 MB
__device__ uint32_t g_front0[BB * WORDS];     // front-sel bits for row 0 of each batch

// ---- threefry2x32, key = (0, 42) baked in ----
__device__ __forceinline__ void threefry_0_42(uint32_t c0, uint32_t c1,
                                              uint32_t& o0, uint32_t& o1) {
    uint32_t x0 = c0 + 0u;
    uint32_t x1 = c1 + 42u;
#define TF_RND(r) { x0 += x1; x1 = __funnelshift_l(x1, x1, (r)); x1 ^= x0; }
    TF_RND(13) TF_RND(15) TF_RND(26) TF_RND(6)
    x0 += 42u;          x1 += 0x1BD11BF1u;
    TF_RND(17) TF_RND(29) TF_RND(16) TF_RND(24)
    x0 += 0x1BD11BF0u;  x1 += 2u;
    TF_RND(13) TF_RND(15) TF_RND(26) TF_RND(6)
    x0 += 0u;           x1 += 45u;
    TF_RND(17) TF_RND(29) TF_RND(16) TF_RND(24)
    x0 += 42u;          x1 += 0x1BD11BF4u;
    TF_RND(13) TF_RND(15) TF_RND(26) TF_RND(6)
    x0 += 0x1BD11BF0u;  x1 += 5u;
#undef TF_RND
    o0 = x0; o1 = x1;
}

// Left-aligned ordering key of jax.random.uniform at flat index g.
// uniform ordering == ordering of (bits & ~0x1FF); low 9 bits are zero.
__device__ __forceinline__ uint32_t rand_key(uint32_t g) {
    uint32_t o0, o1;
    threefry_0_42(0u, g, o0, o1);
    return (o0 ^ o1) & 0xFFFFFE00u;
}

__device__ __forceinline__ uint32_t warp_exscan(uint32_t v, int lane) {
    uint32_t x = v;
#pragma unroll
    for (int d = 1; d < 32; d <<= 1) {
        uint32_t y = __shfl_up_sync(0xFFFFFFFFu, x, d);
        if (lane >= d) x += y;
    }
    return x - v;
}

#define T1  512
#define EPT 8   // 512*8 = 4096 elems

// Launch-index padding so ncu -s 5 -c 1 captures k1 (idx 5 mod 4 == 1).
__global__ void noop_kernel() {}

// ============================================================================
// Kernel 1: one block per score row. Fused dual radix select (front over
// score keys, rand over threefry keys) + packed mask writes.
// ============================================================================
__global__ __launch_bounds__(T1) void k1_select(const float* __restrict__ score) {
    const int q = blockIdx.x;              // row id in [0, 16384)
    const int t = threadIdx.x;
    const int wi = t >> 5, lane = t & 31;
    const uint32_t lmask_lt = (1u << lane) - 1u;

    const float* row = score + (size_t)q * CC;

    __shared__ uint32_t hist[512];         // [0:256) front, [256:512) rand
    __shared__ uint32_t s_ctl[4];          // {pf, kf, pr, kr}
    __shared__ uint32_t s_warp[16];
    __shared__ uint32_t s_c0;
    __shared__ uint32_t s_pre[WORDS];
    __shared__ uint32_t s_pref_f[WORDS];

    // ---- load, key-ify, count rand keys below static pivot ----
    const uint32_t PIV = 1u << 29;   // E[count]=512 >= 409 (5σ margin)
    uint32_t skey[EPT], rkey[EPT];
    uint32_t cnt = 0;
#pragma unroll
    for (int j = 0; j < EPT; j++) {
        int c = j * T1 + t;
        uint32_t u = __float_as_uint(row[c]);
        skey[j] = u ^ ((u & 0x80000000u) ? 0xFFFFFFFFu : 0x80000000u);
        rkey[j] = rand_key((uint32_t)(q * CC + c));
        cnt += __popc(__ballot_sync(0xFFFFFFFFu, rkey[j] < PIV));
    }
    if (lane == 0) s_warp[wi] = cnt;
    __syncthreads();
    if (t == 0) {
        uint32_t s = 0;
#pragma unroll
        for (int i = 0; i < 16; i++) s += s_warp[i];
        s_c0 = s;
    }
    __syncthreads();
    // exact fallback: if pivot cut too tight (~never), scan everything
    const uint32_t rmax = (s_c0 >= (uint32_t)K_RAND) ? PIV : 0xFFFFFFFFu;

    // ---- fused top-down 8-bit radix: front 4 passes, rand 3 passes ----
    uint32_t pf = 0, kf = K_FRONT - 1;     // front prefix / residual rank
    uint32_t pr = 0, kr = K_RAND - 1;      // rand prefix / residual rank

#pragma unroll
    for (int p = 0; p < 4; p++) {
        const int shift = 24 - 8 * p;
        hist[t < 512 ? t : 0] = 0;         // 512 threads zero 512 bins
        __syncthreads();
#pragma unroll
        for (int j = 0; j < EPT; j++) {
            uint32_t kv = skey[j];
            bool mf = (p == 0) || ((kv >> (shift + 8)) == pf);
            if (mf) atomicAdd(&hist[(kv >> shift) & 255u], 1u);
            if (p < 3) {
                uint32_t rv = rkey[j];
                bool mr = (rv < rmax) && (p == 0 || ((rv >> (shift + 8)) == pr));
                if (mr) atomicAdd(&hist[256u + ((rv >> shift) & 255u)], 1u);
            }
        }
        __syncthreads();
        if (t < 64 && (t < 32 || p < 3)) { // warp0: front bins, warp1: rand bins
            const int base = (t < 32) ? 0 : 256;
            const uint32_t kk = (t < 32) ? kf : kr;
            uint32_t h[8]; uint32_t sum = 0;
#pragma unroll
            for (int b2 = 0; b2 < 8; b2++) { h[b2] = hist[base + 8 * lane + b2]; sum += h[b2]; }
            uint32_t run = warp_exscan(sum, lane);
#pragma unroll
            for (int b2 = 0; b2 < 8; b2++) {
                if (kk >= run && kk < run + h[b2]) {
                    const int o = (t < 32) ? 0 : 2;
                    s_ctl[o]     = (uint32_t)(8 * lane + b2);
                    s_ctl[o + 1] = kk - run;
                }
                run += h[b2];
            }
        }
        __syncthreads();
        pf = (pf << 8) | s_ctl[0];
        kf = s_ctl[1];
        if (p < 3) { pr = (pr << 8) | s_ctl[2]; kr = s_ctl[3]; }
        // no extra sync: s_ctl is next written after two more barriers
    }
    const uint32_t Tf = pf;                 // exact 32-bit front threshold
    const uint32_t Tr = pr << 8;            // rand threshold (low 9 bits zero)
    const uint32_t need_f = kf + 1;         // # of ==T taken (lowest index first)
    const uint32_t need_r = kr + 1;

    // ---- exact tie-break: per-word counts of ==T, then exclusive prefix ----
#pragma unroll
    for (int j = 0; j < EPT; j++) {
        uint32_t bf = __ballot_sync(0xFFFFFFFFu, skey[j] == Tf);
        uint32_t br = __ballot_sync(0xFFFFFFFFu, rkey[j] == Tr);
        if (lane == 0) {
            s_pref_f[j * 16 + wi] = __popc(bf);
            s_pre[j * 16 + wi]    = __popc(br);
        }
    }
    __syncthreads();
    if (t < 32) {  // exclusive prefix over 128 words, both arrays
        uint32_t a[4], b[4], sa = 0, sb = 0;
#pragma unroll
        for (int i = 0; i < 4; i++) { a[i] = s_pref_f[4 * t + i]; sa += a[i];
                                      b[i] = s_pre[4 * t + i];    sb += b[i]; }
        uint32_t ea = warp_exscan(sa, t), eb = warp_exscan(sb, t);
#pragma unroll
        for (int i = 0; i < 4; i++) {
            s_pref_f[4 * t + i] = ea; ea += a[i];
            s_pre[4 * t + i]    = eb; eb += b[i];
        }
    }
    __syncthreads();

    // ---- final mask computation + packed writes ----
    const bool is_row0 = ((q & (RR - 1)) == 0);
#pragma unroll
    for (int j = 0; j < EPT; j++) {
        const int w = j * 16 + wi;
        uint32_t bf = __ballot_sync(0xFFFFFFFFu, skey[j] == Tf);
        uint32_t br = __ballot_sync(0xFFFFFFFFu, rkey[j] == Tr);
        bool fsel = (skey[j] < Tf) ||
                    ((skey[j] == Tf) && (s_pref_f[w] + __popc(bf & lmask_lt) < need_f));
        bool rsel = (rkey[j] < Tr) ||
                    ((rkey[j] == Tr) && (s_pre[w] + __popc(br & lmask_lt) < need_r));
        uint32_t keep_w  = __ballot_sync(0xFFFFFFFFu, !(fsel || rsel));
        uint32_t front_w = __ballot_sync(0xFFFFFFFFu, fsel);
        if (lane == 0) {
            g_smask[q * WORDS + w] = keep_w;
            if (is_row0) g_front0[(q >> 11) * WORDS + w] = front_w;
        }
    }
}

// ============================================================================
// Kernel 2: per-batch [4096 x 2048] transpose with mask application.
// ============================================================================
__global__ __launch_bounds__(256) void k2_transpose(const float* __restrict__ score,
                                                    float* __restrict__ out_s,
                                                    float* __restrict__ out_t) {
    __shared__ float ss[32][33];
    __shared__ float st[32][33];
    const int b  = blockIdx.z;
    const int m0 = blockIdx.y * 32;
    const int j0 = blockIdx.x * 32;
    const int tx = threadIdx.x, ty = threadIdx.y;   // (32, 8)

    const float* base = score + (size_t)b * (RR * CC);
#pragma unroll
    for (int k = 0; k < 4; k++) {
        int m = m0 + ty + 8 * k;
        int j = j0 + tx;
        float v = base[(size_t)m * 2048 + j];
        int r = m >> 1;
        int c = ((m & 1) << 11) + j;
        int q = b * RR + r;
        uint32_t mw = g_smask[q * WORDS + (c >> 5)];
        float vs = ((mw >> (c & 31)) & 1u) ? v : 0.0f;
        float vt;
        if (r == 0) {
            uint32_t fw = g_front0[b * WORDS + (c >> 5)];
            vt = ((fw >> (c & 31)) & 1u) ? v : 0.0f;
        } else {
            vt = v;     // reference teacher-mask bug: rows 1.. stay all-ones
        }
        ss[ty + 8 * k][tx] = vs;
        st[ty + 8 * k][tx] = vt;
    }
    __syncthreads();

    float* os = out_s + (size_t)b * (RR * CC);
    float* ot = out_t + (size_t)b * (RR * CC);
#pragma unroll
    for (int k = 0; k < 4; k++) {
        int j = j0 + ty + 8 * k;
        int m = m0 + tx;
        os[(size_t)j * CC + m] = ss[tx][ty + 8 * k];
        ot[(size_t)j * CC + m] = st[tx][ty + 8 * k];
    }
}

// ============================================================================
extern "C" void kernel_launch(void* const* d_in, const int* in_sizes, int n_in,
                              void* d_out, int out_size) {
    const float* score = (const float*)d_in[0];
    float* out = (float*)d_out;
    float* out_teacher = out + (size_t)BB * RR * CC;

    // [noop, k1, k2, noop] per call -> global launch idx 5 is k1 (ncu -s 5 -c 1)
    noop_kernel<<<1, 1>>>();
    k1_select<<<NROWS, T1>>>(score);

    dim3 grid(CC / 2 / 32, CC / 32, BB);
    dim3 blk(32, 8);
    k2_transpose<<<grid, blk>>>(score, out, out_teacher);
    noop_kernel<<<1, 1>>>();
}